// round 4
// baseline (speedup 1.0000x reference)
#include <cuda_runtime.h>

#define S 2048
#define B 32
#define H 1024

#define K1_TH 128
#define K1_KC 64
#define KSPL  (H / K1_KC)   // 16 k-splits

#define EK_WARPS 8          // 256 threads
#define EK_ITERS 4          // 4 iters x 16 rows = 64 s-rows per block
#define EK_ROWS  (EK_WARPS * 2 * EK_ITERS)   // 64
#define NGRP     (S / EK_ROWS)               // 32 s-groups per b

// Scratch (no allocation allowed in kernel_launch)
__device__ float  g_vpart[KSPL][B][H];   // per-ksplit partials of v (2 MB)
__device__ float  g_v[B * H];            // v[b,h] = sum_k dec[b,k] * W[k,h]
__device__ float  g_energy[B * S];       // energies[b,s]
__device__ float2 g_stats[B][NGRP];      // per-(b,sgroup) (max, expsum)

// ---------------------------------------------------------------------------
// Partial v: g_vpart[split][b][h] = sum_{k in split} dec[b,k] * W[k,h]
// grid: (H/K1_TH, KSPL) = (8, 16) = 128 blocks; one h per thread. No atomics.
__global__ __launch_bounds__(K1_TH) void proj_kernel(
    const float* __restrict__ dec,   // [B, H]
    const float* __restrict__ W)     // [H, H], W[k*H + h]
{
    __shared__ float s_dec[B][K1_KC];
    const int h  = blockIdx.x * K1_TH + threadIdx.x;
    const int k0 = blockIdx.y * K1_KC;

    for (int i = threadIdx.x; i < B * K1_KC; i += K1_TH) {
        int b = i / K1_KC, k = i % K1_KC;
        s_dec[b][k] = dec[b * H + k0 + k];
    }
    __syncthreads();

    float acc[B];
#pragma unroll
    for (int b = 0; b < B; b++) acc[b] = 0.0f;

#pragma unroll
    for (int kk = 0; kk < K1_KC; kk += 8) {
        float w[8];
#pragma unroll
        for (int u = 0; u < 8; u++)
            w[u] = __ldg(&W[(size_t)(k0 + kk + u) * H + h]);
#pragma unroll
        for (int u = 0; u < 8; u++) {
#pragma unroll
            for (int b = 0; b < B; b++)
                acc[b] = fmaf(s_dec[b][kk + u], w[u], acc[b]);
        }
    }

#pragma unroll
    for (int b = 0; b < B; b++)
        g_vpart[blockIdx.y][b][h] = acc[b];
}

// ---------------------------------------------------------------------------
// v[b,h] = sum_split g_vpart[split][b][h].  float4 per thread.
__global__ __launch_bounds__(128) void reduce_v_kernel()
{
    const int i4 = blockIdx.x * blockDim.x + threadIdx.x;   // [0, B*H/4)
    const float4* src = reinterpret_cast<const float4*>(&g_vpart[0][0][0]);
    float4 acc = src[i4];
#pragma unroll
    for (int s = 1; s < KSPL; s++) {
        float4 p = src[(size_t)s * (B * H / 4) + i4];
        acc.x += p.x; acc.y += p.y; acc.z += p.z; acc.w += p.w;
    }
    reinterpret_cast<float4*>(g_v)[i4] = acc;
}

// ---------------------------------------------------------------------------
// energies[b,s] = v[b] . enc[s,b,:]  + per-block softmax stats (max, expsum).
// Each block: one b, 64 consecutive s-rows (4 iters x 8 warps x 2 rows).
// grid: B * NGRP = 1024 blocks of 256 threads.
__global__ __launch_bounds__(32 * EK_WARPS) void energy_kernel(
    const float* __restrict__ enc)   // [S, B, H]
{
    __shared__ float4 s_v[H / 4];
    __shared__ float  s_e[EK_ROWS];

    const int b    = blockIdx.x >> 5;        // / NGRP
    const int sg   = blockIdx.x & (NGRP - 1);
    const int warp = threadIdx.x >> 5;
    const int lane = threadIdx.x & 31;

    const float4* vb = reinterpret_cast<const float4*>(&g_v[b * H]);
    for (int i = threadIdx.x; i < H / 4; i += blockDim.x) s_v[i] = vb[i];
    __syncthreads();

    const int sbase = sg * EK_ROWS;

#pragma unroll
    for (int it = 0; it < EK_ITERS; it++) {
        const int r0 = it * 16 + warp;           // local row (warp)
        const int r1 = r0 + EK_WARPS;            // local row (warp, +8)
        const int s0 = sbase + r0;
        const int s1 = sbase + r1;

        const float4* e0 =
            reinterpret_cast<const float4*>(&enc[((size_t)s0 * B + b) * (size_t)H]);
        const float4* e1 =
            reinterpret_cast<const float4*>(&enc[((size_t)s1 * B + b) * (size_t)H]);

        float acc0 = 0.0f, acc1 = 0.0f;
#pragma unroll
        for (int j = 0; j < (H / 4) / 32; j++) {
            float4 a = __ldcs(&e0[lane + j * 32]);
            float4 c = __ldcs(&e1[lane + j * 32]);
            float4 vv = s_v[lane + j * 32];
            acc0 = fmaf(a.x, vv.x, acc0);
            acc0 = fmaf(a.y, vv.y, acc0);
            acc0 = fmaf(a.z, vv.z, acc0);
            acc0 = fmaf(a.w, vv.w, acc0);
            acc1 = fmaf(c.x, vv.x, acc1);
            acc1 = fmaf(c.y, vv.y, acc1);
            acc1 = fmaf(c.z, vv.z, acc1);
            acc1 = fmaf(c.w, vv.w, acc1);
        }

#pragma unroll
        for (int o = 16; o > 0; o >>= 1) {
            acc0 += __shfl_down_sync(0xffffffffu, acc0, o);
            acc1 += __shfl_down_sync(0xffffffffu, acc1, o);
        }

        if (lane == 0) {
            g_energy[b * S + s0] = acc0;
            g_energy[b * S + s1] = acc1;
            s_e[r0] = acc0;
            s_e[r1] = acc1;
        }
    }
    __syncthreads();

    // Block softmax stats over its 64 energies (single warp).
    if (warp == 0) {
        float a = s_e[lane], c = s_e[lane + 32];
        float m = fmaxf(a, c);
#pragma unroll
        for (int o = 16; o > 0; o >>= 1)
            m = fmaxf(m, __shfl_xor_sync(0xffffffffu, m, o));
        float sum = __expf(a - m) + __expf(c - m);
#pragma unroll
        for (int o = 16; o > 0; o >>= 1)
            sum += __shfl_xor_sync(0xffffffffu, sum, o);
        if (lane == 0) g_stats[b][sg] = make_float2(m, sum);
    }
}

// ---------------------------------------------------------------------------
// Normalize: combine 32 partial stats per b, then out = exp(e - m) / sum.
// grid: (S/512, B) = (4, 32) = 128 blocks of 256 threads, 2 elems/thread.
__global__ __launch_bounds__(256) void normalize_kernel(float* __restrict__ out)
{
    __shared__ float sh_m, sh_inv;
    const int b   = blockIdx.y;
    const int tid = threadIdx.x;

    if (tid < 32) {
        float2 st = g_stats[b][tid];
        float m = st.x;
#pragma unroll
        for (int o = 16; o > 0; o >>= 1)
            m = fmaxf(m, __shfl_xor_sync(0xffffffffu, m, o));
        float sum = st.y * __expf(st.x - m);
#pragma unroll
        for (int o = 16; o > 0; o >>= 1)
            sum += __shfl_xor_sync(0xffffffffu, sum, o);
        if (tid == 0) { sh_m = m; sh_inv = __frcp_rn(sum); }
    }
    __syncthreads();

    const float m = sh_m, inv = sh_inv;
    const int base = blockIdx.x * 512;
#pragma unroll
    for (int j = 0; j < 2; j++) {
        int idx = base + tid + j * 256;
        out[b * S + idx] = __expf(g_energy[b * S + idx] - m) * inv;
    }
}

// ---------------------------------------------------------------------------
extern "C" void kernel_launch(void* const* d_in, const int* in_sizes, int n_in,
                              void* d_out, int out_size)
{
    const float* dec = (const float*)d_in[0];   // rnn_outputs [1,B,H]
    const float* enc = (const float*)d_in[1];   // encoder_outputs [S,B,H]
    const float* W   = (const float*)d_in[2];   // W_attn [H,H]
    // d_in[3] = b_attn: constant over s per batch -> cancelled by softmax.
    float* out = (float*)d_out;                 // [B,S] float32

    proj_kernel<<<dim3(H / K1_TH, KSPL), K1_TH>>>(dec, W);
    reduce_v_kernel<<<(B * H / 4) / 128, 128>>>();
    energy_kernel<<<B * NGRP, 32 * EK_WARPS>>>(enc);
    normalize_kernel<<<dim3(S / 512, B), 256>>>(out);
}

// round 5
// speedup vs baseline: 1.1716x; 1.1716x over previous
#include <cuda_runtime.h>

#define S 2048
#define B 32
#define H 1024

#define K1_TH 128
#define K1_KC 64
#define KSPL  (H / K1_KC)   // 16 k-splits

#define K2_WARPS 8
#define K2_ROWS (K2_WARPS * 2)      // 16 s-rows per block
#define NGRP    (S / K2_ROWS)       // 128 s-groups per b

// Scratch (no allocation allowed in kernel_launch)
__device__ float  g_vpart[KSPL][B][H];   // per-ksplit partials of v (2 MB)
__device__ float  g_v[B * H];            // v[b,h]
__device__ float  g_energy[B * S];       // energies[b,s]
__device__ float2 g_stats[B][NGRP];      // per-(b,sgroup) (max, expsum)

// ---------------------------------------------------------------------------
// Partial v: g_vpart[split][b][h] = sum_{k in split} dec[b,k] * W[k,h]
__global__ __launch_bounds__(K1_TH) void proj_kernel(
    const float* __restrict__ dec,   // [B, H]
    const float* __restrict__ W)     // [H, H], W[k*H + h]
{
    __shared__ float s_dec[B][K1_KC];
    const int h  = blockIdx.x * K1_TH + threadIdx.x;
    const int k0 = blockIdx.y * K1_KC;

    for (int i = threadIdx.x; i < B * K1_KC; i += K1_TH) {
        int b = i / K1_KC, k = i % K1_KC;
        s_dec[b][k] = dec[b * H + k0 + k];
    }
    __syncthreads();

    float acc[B];
#pragma unroll
    for (int b = 0; b < B; b++) acc[b] = 0.0f;

#pragma unroll
    for (int kk = 0; kk < K1_KC; kk += 8) {
        float w[8];
#pragma unroll
        for (int u = 0; u < 8; u++)
            w[u] = __ldg(&W[(size_t)(k0 + kk + u) * H + h]);
#pragma unroll
        for (int u = 0; u < 8; u++) {
#pragma unroll
            for (int b = 0; b < B; b++)
                acc[b] = fmaf(s_dec[b][kk + u], w[u], acc[b]);
        }
    }

#pragma unroll
    for (int b = 0; b < B; b++)
        g_vpart[blockIdx.y][b][h] = acc[b];
}

// ---------------------------------------------------------------------------
// v[b,h] = sum_split g_vpart[split][b][h].  float4 per thread.
__global__ __launch_bounds__(128) void reduce_v_kernel()
{
    const int i4 = blockIdx.x * blockDim.x + threadIdx.x;   // [0, B*H/4)
    const float4* src = reinterpret_cast<const float4*>(&g_vpart[0][0][0]);
    float4 acc = src[i4];
#pragma unroll
    for (int s = 1; s < KSPL; s++) {
        float4 p = src[(size_t)s * (B * H / 4) + i4];
        acc.x += p.x; acc.y += p.y; acc.z += p.z; acc.w += p.w;
    }
    reinterpret_cast<float4*>(g_v)[i4] = acc;
}

// ---------------------------------------------------------------------------
// energies[b,s] = v[b] . enc[s,b,:]  (R2 shape) + per-block (max, expsum).
// grid: (S/K2_ROWS, B) = (128, 32) = 4096 blocks of 256 threads.
__global__ __launch_bounds__(32 * K2_WARPS) void energy_kernel(
    const float* __restrict__ enc)   // [S, B, H]
{
    __shared__ float4 s_v[H / 4];
    __shared__ float  s_e[K2_ROWS];
    const int b = blockIdx.y;

    const float4* vb = reinterpret_cast<const float4*>(&g_v[b * H]);
    for (int i = threadIdx.x; i < H / 4; i += blockDim.x) s_v[i] = vb[i];
    __syncthreads();

    const int warp = threadIdx.x >> 5;
    const int lane = threadIdx.x & 31;
    const int s0 = blockIdx.x * K2_ROWS + warp;          // row 1
    const int s1 = s0 + K2_WARPS;                        // row 2

    const float4* e0 =
        reinterpret_cast<const float4*>(&enc[((size_t)s0 * B + b) * (size_t)H]);
    const float4* e1 =
        reinterpret_cast<const float4*>(&enc[((size_t)s1 * B + b) * (size_t)H]);

    float acc0 = 0.0f, acc1 = 0.0f;
#pragma unroll
    for (int j = 0; j < (H / 4) / 32; j++) {   // 8 float4 iterations per row
        float4 a = __ldcs(&e0[lane + j * 32]);
        float4 c = __ldcs(&e1[lane + j * 32]);
        float4 vv = s_v[lane + j * 32];
        acc0 = fmaf(a.x, vv.x, acc0);
        acc0 = fmaf(a.y, vv.y, acc0);
        acc0 = fmaf(a.z, vv.z, acc0);
        acc0 = fmaf(a.w, vv.w, acc0);
        acc1 = fmaf(c.x, vv.x, acc1);
        acc1 = fmaf(c.y, vv.y, acc1);
        acc1 = fmaf(c.z, vv.z, acc1);
        acc1 = fmaf(c.w, vv.w, acc1);
    }

#pragma unroll
    for (int o = 16; o > 0; o >>= 1) {
        acc0 += __shfl_down_sync(0xffffffffu, acc0, o);
        acc1 += __shfl_down_sync(0xffffffffu, acc1, o);
    }

    if (lane == 0) {
        g_energy[b * S + s0] = acc0;
        g_energy[b * S + s1] = acc1;
        s_e[warp] = acc0;
        s_e[warp + K2_WARPS] = acc1;
    }
    __syncthreads();

    // One warp reduces the block's 16 energies to (max, expsum).
    if (warp == 0 && lane < K2_ROWS) {
        float e = s_e[lane];
        float m = e;
#pragma unroll
        for (int o = 8; o > 0; o >>= 1)
            m = fmaxf(m, __shfl_xor_sync(0x0000ffffu, m, o));
        float sum = __expf(e - m);
#pragma unroll
        for (int o = 8; o > 0; o >>= 1)
            sum += __shfl_xor_sync(0x0000ffffu, sum, o);
        if (lane == 0) g_stats[b][blockIdx.x] = make_float2(m, sum);
    }
}

// ---------------------------------------------------------------------------
// Normalize: combine NGRP=128 partial stats per b, out = exp(e - m) * inv.
// grid: (S/512, B) = (4, 32) = 128 blocks of 256 threads, 2 elems/thread.
__global__ __launch_bounds__(256) void normalize_kernel(float* __restrict__ out)
{
    __shared__ float sh_m, sh_inv;
    const int b   = blockIdx.y;
    const int tid = threadIdx.x;

    if (tid < 32) {
        float m = -1e30f;
        float2 st[NGRP / 32];
#pragma unroll
        for (int j = 0; j < NGRP / 32; j++) {
            st[j] = g_stats[b][tid + j * 32];
            m = fmaxf(m, st[j].x);
        }
#pragma unroll
        for (int o = 16; o > 0; o >>= 1)
            m = fmaxf(m, __shfl_xor_sync(0xffffffffu, m, o));
        float sum = 0.0f;
#pragma unroll
        for (int j = 0; j < NGRP / 32; j++)
            sum += st[j].y * __expf(st[j].x - m);
#pragma unroll
        for (int o = 16; o > 0; o >>= 1)
            sum += __shfl_xor_sync(0xffffffffu, sum, o);
        if (tid == 0) { sh_m = m; sh_inv = __frcp_rn(sum); }
    }
    __syncthreads();

    const float m = sh_m, inv = sh_inv;
    const int base = blockIdx.x * 512;
#pragma unroll
    for (int j = 0; j < 2; j++) {
        int idx = base + tid + j * 256;
        out[b * S + idx] = __expf(g_energy[b * S + idx] - m) * inv;
    }
}

// ---------------------------------------------------------------------------
extern "C" void kernel_launch(void* const* d_in, const int* in_sizes, int n_in,
                              void* d_out, int out_size)
{
    const float* dec = (const float*)d_in[0];   // rnn_outputs [1,B,H]
    const float* enc = (const float*)d_in[1];   // encoder_outputs [S,B,H]
    const float* W   = (const float*)d_in[2];   // W_attn [H,H]
    // d_in[3] = b_attn: constant over s per batch -> cancelled by softmax.
    float* out = (float*)d_out;                 // [B,S] float32

    proj_kernel<<<dim3(H / K1_TH, KSPL), K1_TH>>>(dec, W);
    reduce_v_kernel<<<(B * H / 4) / 128, 128>>>();
    energy_kernel<<<dim3(S / K2_ROWS, B), 32 * K2_WARPS>>>(enc);
    normalize_kernel<<<dim3(S / 512, B), 256>>>(out);
}

// round 6
// speedup vs baseline: 1.3176x; 1.1246x over previous
#include <cuda_runtime.h>

#define S 2048
#define B 32
#define H 1024

#define K1_TH 128
#define K1_KC 32

#define K2_WARPS 8
#define K2_ROWS (K2_WARPS * 2)

// Scratch (no allocation in kernel_launch). Zero-initialized at module load;
// softmax_kernel re-zeroes g_v every call, so every graph replay starts clean.
__device__ float g_v[B * H];        // v[b,h] = sum_k dec[b,k] * W[k,h]
__device__ float g_energy[B * S];   // energies[b,s]

// ---------------------------------------------------------------------------
// v[b,h] += sum_{k in chunk} dec[b,k] * W[k,h]
// grid: (H/K1_TH, H/K1_KC) = (8, 32) = 256 blocks; one h per thread.
__global__ __launch_bounds__(K1_TH) void proj_kernel(
    const float* __restrict__ dec,   // [B, H]
    const float* __restrict__ W)     // [H, H], W[k*H + h]
{
    __shared__ float s_dec[B][K1_KC];
    const int h  = blockIdx.x * K1_TH + threadIdx.x;
    const int k0 = blockIdx.y * K1_KC;

    for (int i = threadIdx.x; i < B * K1_KC; i += K1_TH) {
        int b = i / K1_KC, k = i % K1_KC;
        s_dec[b][k] = dec[b * H + k0 + k];
    }
    __syncthreads();

    float acc[B];
#pragma unroll
    for (int b = 0; b < B; b++) acc[b] = 0.0f;

#pragma unroll
    for (int kk = 0; kk < K1_KC; kk += 8) {
        float w[8];
#pragma unroll
        for (int u = 0; u < 8; u++)
            w[u] = __ldg(&W[(size_t)(k0 + kk + u) * H + h]);
#pragma unroll
        for (int u = 0; u < 8; u++) {
#pragma unroll
            for (int b = 0; b < B; b++)
                acc[b] = fmaf(s_dec[b][kk + u], w[u], acc[b]);
        }
    }

#pragma unroll
    for (int b = 0; b < B; b++)
        atomicAdd(&g_v[b * H + h], acc[b]);
}

// ---------------------------------------------------------------------------
// energies[b,s] = v[b] . enc[s,b,:]   (dominant, streams 256 MB)
// One warp handles TWO s-rows. grid: (S/K2_ROWS, B) = (128, 32) = 4096 blocks.
__global__ __launch_bounds__(32 * K2_WARPS) void energy_kernel(
    const float* __restrict__ enc)   // [S, B, H]
{
    __shared__ float4 s_v[H / 4];
    const int b = blockIdx.y;

    const float4* vb = reinterpret_cast<const float4*>(&g_v[b * H]);
    for (int i = threadIdx.x; i < H / 4; i += blockDim.x) s_v[i] = vb[i];
    __syncthreads();

    const int warp = threadIdx.x >> 5;
    const int lane = threadIdx.x & 31;
    const int s0 = blockIdx.x * K2_ROWS + warp;          // row 1
    const int s1 = s0 + K2_WARPS;                        // row 2

    const float4* e0 =
        reinterpret_cast<const float4*>(&enc[((size_t)s0 * B + b) * (size_t)H]);
    const float4* e1 =
        reinterpret_cast<const float4*>(&enc[((size_t)s1 * B + b) * (size_t)H]);

    float acc0 = 0.0f, acc1 = 0.0f;
#pragma unroll
    for (int j = 0; j < (H / 4) / 32; j++) {   // 8 float4 iterations per row
        float4 a = __ldcs(&e0[lane + j * 32]); // streaming: don't pollute L2
        float4 c = __ldcs(&e1[lane + j * 32]);
        float4 vv = s_v[lane + j * 32];
        acc0 = fmaf(a.x, vv.x, acc0);
        acc0 = fmaf(a.y, vv.y, acc0);
        acc0 = fmaf(a.z, vv.z, acc0);
        acc0 = fmaf(a.w, vv.w, acc0);
        acc1 = fmaf(c.x, vv.x, acc1);
        acc1 = fmaf(c.y, vv.y, acc1);
        acc1 = fmaf(c.z, vv.z, acc1);
        acc1 = fmaf(c.w, vv.w, acc1);
    }

#pragma unroll
    for (int o = 16; o > 0; o >>= 1) {
        acc0 += __shfl_down_sync(0xffffffffu, acc0, o);
        acc1 += __shfl_down_sync(0xffffffffu, acc1, o);
    }

    if (lane == 0) {
        g_energy[b * S + s0] = acc0;
        g_energy[b * S + s1] = acc1;
    }
}

// ---------------------------------------------------------------------------
// softmax over s for each b; also re-zeroes g_v[b] for the next replay.
// grid: B blocks of 1024 threads, 2 elems/thread.
#define K3_TH 1024
__global__ __launch_bounds__(K3_TH) void softmax_kernel(float* __restrict__ out)
{
    __shared__ float red[K3_TH / 32];
    const int b = blockIdx.x;
    const int tid = threadIdx.x;
    const int lane = tid & 31, warp = tid >> 5;
    const float* e = &g_energy[b * S];

    // Re-zero g_v[b,:] (consumed by energy_kernel already). 1024 threads,
    // 1 float each: keeps every replay's proj_kernel accumulating from zero.
    g_v[b * H + tid] = 0.0f;

    float vals[S / K3_TH];
    float m = -1e30f;
#pragma unroll
    for (int j = 0; j < S / K3_TH; j++) {
        vals[j] = e[tid + j * K3_TH];
        m = fmaxf(m, vals[j]);
    }
#pragma unroll
    for (int o = 16; o > 0; o >>= 1)
        m = fmaxf(m, __shfl_xor_sync(0xffffffffu, m, o));
    if (lane == 0) red[warp] = m;
    __syncthreads();
#pragma unroll
    for (int w = 0; w < K3_TH / 32; w++) m = fmaxf(m, red[w]);
    __syncthreads();

    float sum = 0.0f;
#pragma unroll
    for (int j = 0; j < S / K3_TH; j++) {
        vals[j] = __expf(vals[j] - m);
        sum += vals[j];
    }
#pragma unroll
    for (int o = 16; o > 0; o >>= 1)
        sum += __shfl_xor_sync(0xffffffffu, sum, o);
    if (lane == 0) red[warp] = sum;
    __syncthreads();
    float total = 0.0f;
#pragma unroll
    for (int w = 0; w < K3_TH / 32; w++) total += red[w];

    const float inv = __frcp_rn(total);
#pragma unroll
    for (int j = 0; j < S / K3_TH; j++)
        out[b * S + tid + j * K3_TH] = vals[j] * inv;
}

// ---------------------------------------------------------------------------
extern "C" void kernel_launch(void* const* d_in, const int* in_sizes, int n_in,
                              void* d_out, int out_size)
{
    const float* dec = (const float*)d_in[0];   // rnn_outputs [1,B,H]
    const float* enc = (const float*)d_in[1];   // encoder_outputs [S,B,H]
    const float* W   = (const float*)d_in[2];   // W_attn [H,H]
    // d_in[3] = b_attn: constant over s per batch -> cancelled by softmax.
    float* out = (float*)d_out;                 // [B,S] float32

    proj_kernel<<<dim3(H / K1_TH, H / K1_KC), K1_TH>>>(dec, W);
    energy_kernel<<<dim3(S / K2_ROWS, B), 32 * K2_WARPS>>>(enc);
    softmax_kernel<<<B, K3_TH>>>(out);
}